// round 7
// baseline (speedup 1.0000x reference)
#include <cuda_runtime.h>

// ============================================================================
// ExampleModel_9234179686517: grid_sample(border,bilinear) + 5-layer MLP (HID=16)
//
// Inputs (metadata order):
//   d_in[0]  x           (N,3)       float32   N = 4,000,000
//   d_in[1]  featuremap  (4,512,512) float32
//   d_in[2]  W1 (7,16)   d_in[3]  b1 (16)
//   d_in[4]  W2 (16,16)  d_in[5]  b2 (16)
//   d_in[6]  W3 (16,16)  d_in[7]  b3 (16)
//   d_in[8]  W4 (16,16)  d_in[9]  b4 (16)
//   d_in[10] W5 (16,3)   d_in[11] b5 (3)
// Output: (N,3) float32
//
// Strategy:
//   Kernel 1: transpose featuremap CHW -> HWC float4 (one 16B load per corner).
//   Kernel 2: 4 points per thread, packed as 2x f32x2 pairs. Weights duplicated
//   (w,w) as float2 in shared; one broadcast LDS.64 feeds two fma.rn.f32x2
//   (4 FMAs). FMA-pipe bound.
// ============================================================================

#define FM_HW   512
#define FM_NPIX (FM_HW * FM_HW)

__device__ float4 g_fmT[FM_NPIX];   // 4 MB scratch (allowed: __device__ global)

typedef unsigned long long u64;

__device__ __forceinline__ float2 ffma2(float2 a, float2 b, float2 c) {
    u64 ra, rb, rc, rd;
    asm("mov.b64 %0, {%1, %2};" : "=l"(ra) : "f"(a.x), "f"(a.y));
    asm("mov.b64 %0, {%1, %2};" : "=l"(rb) : "f"(b.x), "f"(b.y));
    asm("mov.b64 %0, {%1, %2};" : "=l"(rc) : "f"(c.x), "f"(c.y));
    asm("fma.rn.f32x2 %0, %1, %2, %3;" : "=l"(rd) : "l"(ra), "l"(rb), "l"(rc));
    float2 d;
    asm("mov.b64 {%0, %1}, %2;" : "=f"(d.x), "=f"(d.y) : "l"(rd));
    return d;
}

// ---------------------------------------------------------------------------
// Kernel 1: CHW -> HWC transpose of the featuremap
// ---------------------------------------------------------------------------
__global__ void fm_transpose_kernel(const float* __restrict__ fm) {
    int idx = blockIdx.x * blockDim.x + threadIdx.x;
    if (idx >= FM_NPIX) return;
    g_fmT[idx] = make_float4(fm[idx],
                             fm[idx + FM_NPIX],
                             fm[idx + 2 * FM_NPIX],
                             fm[idx + 3 * FM_NPIX]);
}

// ---------------------------------------------------------------------------
// Bilinear sample with border clamp (matches reference math)
// ---------------------------------------------------------------------------
__device__ __forceinline__ void sample_point(float ux, float uy, float ft[4]) {
    const float w = (float)FM_HW;
    float gx = ux * 2.0f - 1.0f;
    float gy = uy * 2.0f - 1.0f;
    float fx = fminf(fmaxf(((gx + 1.0f) * w - 1.0f) * 0.5f, 0.0f), w - 1.0f);
    float fy = fminf(fmaxf(((gy + 1.0f) * w - 1.0f) * 0.5f, 0.0f), w - 1.0f);
    float x0f = floorf(fx);
    float y0f = floorf(fy);
    float wx1 = fx - x0f;
    float wy1 = fy - y0f;
    int ix0 = (int)x0f;
    int iy0 = (int)y0f;
    int ix1 = min(ix0 + 1, FM_HW - 1);
    int iy1 = min(iy0 + 1, FM_HW - 1);

    float4 v00 = __ldg(&g_fmT[iy0 * FM_HW + ix0]);
    float4 v01 = __ldg(&g_fmT[iy0 * FM_HW + ix1]);
    float4 v10 = __ldg(&g_fmT[iy1 * FM_HW + ix0]);
    float4 v11 = __ldg(&g_fmT[iy1 * FM_HW + ix1]);

    float w00 = (1.0f - wy1) * (1.0f - wx1);
    float w01 = (1.0f - wy1) * wx1;
    float w10 = wy1 * (1.0f - wx1);
    float w11 = wy1 * wx1;

    ft[0] = v00.x * w00 + v01.x * w01 + v10.x * w10 + v11.x * w11;
    ft[1] = v00.y * w00 + v01.y * w01 + v10.y * w10 + v11.y * w11;
    ft[2] = v00.z * w00 + v01.z * w01 + v10.z * w10 + v11.z * w11;
    ft[3] = v00.w * w00 + v01.w * w01 + v10.w * w10 + v11.w * w11;
}

// ---------------------------------------------------------------------------
// Dense layer on 2 packed point-pairs: out[2][NOUT] = (relu?)(in @ W + b)
// sW holds (w,w) duplicated float2; broadcast LDS, each weight feeds 2 FFMA2.
// ---------------------------------------------------------------------------
template<int NIN, int NOUT, bool RELU>
__device__ __forceinline__ void dense(const float2* __restrict__ sW,
                                      const float2* __restrict__ sB,
                                      const float2 (&in)[2][16],
                                      float2 (&out)[2][16]) {
#pragma unroll
    for (int j = 0; j < NOUT; j++) {
        float2 b = sB[j];
        out[0][j] = b;
        out[1][j] = b;
    }
#pragma unroll
    for (int i = 0; i < NIN; i++) {
#pragma unroll
        for (int j = 0; j < NOUT; j++) {
            float2 wv = sW[i * NOUT + j];
            out[0][j] = ffma2(in[0][i], wv, out[0][j]);
            out[1][j] = ffma2(in[1][i], wv, out[1][j]);
        }
    }
    if (RELU) {
#pragma unroll
        for (int j = 0; j < NOUT; j++) {
            out[0][j].x = fmaxf(out[0][j].x, 0.0f);
            out[0][j].y = fmaxf(out[0][j].y, 0.0f);
            out[1][j].x = fmaxf(out[1][j].x, 0.0f);
            out[1][j].y = fmaxf(out[1][j].y, 0.0f);
        }
    }
}

// ---------------------------------------------------------------------------
// Kernel 2: fused sample + MLP, 4 points per thread
// ---------------------------------------------------------------------------
__global__ __launch_bounds__(128)
void mlp_kernel(const float* __restrict__ x,
                const float* __restrict__ W1, const float* __restrict__ b1,
                const float* __restrict__ W2, const float* __restrict__ b2,
                const float* __restrict__ W3, const float* __restrict__ b3,
                const float* __restrict__ W4, const float* __restrict__ b4,
                const float* __restrict__ W5, const float* __restrict__ b5,
                float* __restrict__ outp, int N) {
    __shared__ float2 sW1[7 * 16],  sB1[16];
    __shared__ float2 sW2[16 * 16], sB2[16];
    __shared__ float2 sW3[16 * 16], sB3[16];
    __shared__ float2 sW4[16 * 16], sB4[16];
    __shared__ float2 sW5[16 * 3],  sB5[3];

    int tid = threadIdx.x;
#define LOADW(dst, src, n) \
    for (int i = tid; i < (n); i += blockDim.x) { float v = (src)[i]; (dst)[i] = make_float2(v, v); }
    LOADW(sW1, W1, 7 * 16)   LOADW(sB1, b1, 16)
    LOADW(sW2, W2, 16 * 16)  LOADW(sB2, b2, 16)
    LOADW(sW3, W3, 16 * 16)  LOADW(sB3, b3, 16)
    LOADW(sW4, W4, 16 * 16)  LOADW(sB4, b4, 16)
    LOADW(sW5, W5, 16 * 3)   LOADW(sB5, b5, 3)
#undef LOADW
    __syncthreads();

    long long t = (long long)blockIdx.x * blockDim.x + threadIdx.x;
    long long base = t * 4;
    if (base >= N) return;
    bool full = (base + 4 <= N);

    // ---- load x for 4 points ----
    float px[4][3];
    if (full) {
        const float4* xv = reinterpret_cast<const float4*>(x + base * 3);
        float4 A = xv[0], B = xv[1], C = xv[2];
        px[0][0] = A.x; px[0][1] = A.y; px[0][2] = A.z;
        px[1][0] = A.w; px[1][1] = B.x; px[1][2] = B.y;
        px[2][0] = B.z; px[2][1] = B.w; px[2][2] = C.x;
        px[3][0] = C.y; px[3][1] = C.z; px[3][2] = C.w;
    } else {
#pragma unroll
        for (int p = 0; p < 4; p++) {
            long long idx = base + p;
            if (idx < N) {
                px[p][0] = x[idx * 3 + 0];
                px[p][1] = x[idx * 3 + 1];
                px[p][2] = x[idx * 3 + 2];
            } else {
                px[p][0] = px[p][1] = px[p][2] = 0.0f;
            }
        }
    }

    // ---- bilinear sample 4 points ----
    float ft[4][4];
#pragma unroll
    for (int p = 0; p < 4; p++) sample_point(px[p][0], px[p][1], ft[p]);

    // ---- pack into two f32x2 pairs: pair pr = points (2*pr, 2*pr+1) ----
    float2 h[2][16], g[2][16];
#pragma unroll
    for (int pr = 0; pr < 2; pr++) {
        int p0 = 2 * pr, p1 = 2 * pr + 1;
        h[pr][0] = make_float2(px[p0][0], px[p1][0]);
        h[pr][1] = make_float2(px[p0][1], px[p1][1]);
        h[pr][2] = make_float2(px[p0][2], px[p1][2]);
#pragma unroll
        for (int c = 0; c < 4; c++)
            h[pr][3 + c] = make_float2(ft[p0][c], ft[p1][c]);
    }

    // ---- MLP ----
    dense<7, 16, true >(sW1, sB1, h, g);
    dense<16, 16, true>(sW2, sB2, g, h);
    dense<16, 16, true>(sW3, sB3, h, g);
    dense<16, 16, true>(sW4, sB4, g, h);
    dense<16, 3, false>(sW5, sB5, h, g);   // g[pr][0..2] = outputs

    // ---- unpack + store ----
    float o[4][3];
#pragma unroll
    for (int pr = 0; pr < 2; pr++) {
#pragma unroll
        for (int j = 0; j < 3; j++) {
            o[2 * pr][j]     = g[pr][j].x;
            o[2 * pr + 1][j] = g[pr][j].y;
        }
    }
    if (full) {
        float4* ov = reinterpret_cast<float4*>(outp + base * 3);
        ov[0] = make_float4(o[0][0], o[0][1], o[0][2], o[1][0]);
        ov[1] = make_float4(o[1][1], o[1][2], o[2][0], o[2][1]);
        ov[2] = make_float4(o[2][2], o[3][0], o[3][1], o[3][2]);
    } else {
#pragma unroll
        for (int p = 0; p < 4; p++) {
            long long idx = base + p;
            if (idx < N) {
                outp[idx * 3 + 0] = o[p][0];
                outp[idx * 3 + 1] = o[p][1];
                outp[idx * 3 + 2] = o[p][2];
            }
        }
    }
}

// ---------------------------------------------------------------------------
extern "C" void kernel_launch(void* const* d_in, const int* in_sizes, int n_in,
                              void* d_out, int out_size) {
    const float* x  = (const float*)d_in[0];
    const float* fm = (const float*)d_in[1];
    const float* W1 = (const float*)d_in[2];
    const float* b1 = (const float*)d_in[3];
    const float* W2 = (const float*)d_in[4];
    const float* b2 = (const float*)d_in[5];
    const float* W3 = (const float*)d_in[6];
    const float* b3 = (const float*)d_in[7];
    const float* W4 = (const float*)d_in[8];
    const float* b4 = (const float*)d_in[9];
    const float* W5 = (const float*)d_in[10];
    const float* b5 = (const float*)d_in[11];
    float* outp = (float*)d_out;

    int N = in_sizes[0] / 3;

    // Kernel 1: featuremap CHW -> HWC
    fm_transpose_kernel<<<(FM_NPIX + 255) / 256, 256>>>(fm);

    // Kernel 2: fused sample + MLP, 4 points/thread
    int nthreads = (N + 3) / 4;
    int nblocks  = (nthreads + 127) / 128;
    mlp_kernel<<<nblocks, 128>>>(x, W1, b1, W2, b2, W3, b3, W4, b4, W5, b5,
                                 outp, N);
}